// round 1
// baseline (speedup 1.0000x reference)
#include <cuda_runtime.h>
#include <math.h>

// Problem geometry (fixed by setup_inputs): B=16, C=3, H=W=512
#define NIMG   48
#define HDIM   512
#define WDIM   512
#define LIMG   (HDIM*WDIM)        // 262144 elements per "row" (image)
#define NELEM  (NIMG*LIMG)        // 12,582,912
#define WPR    (WDIM/32)          // 16 mask words per image row
#define WPI    (HDIM*WPR)         // 8192 words per image
#define NWORDS (NIMG*WPI)         // 393,216
#define CHUNK  4096
#define CPI    (LIMG/CHUNK)       // 64 chunks per image
#define NCHUNK (NIMG*CPI)         // 3072
#define LOSS_BLK_ELEMS 2048
#define LOSS_BLOCKS (NELEM/LOSS_BLK_ELEMS)   // 6144

// ---- scratch (no dynamic allocation allowed) ----
__device__ float    gP[NELEM];           // compacted x at (t>0), per image, original order
__device__ float    gF[NELEM];           // compacted x at chosen mask, per image
__device__ unsigned gTB[NWORDS];         // packed bits: t > 0
__device__ unsigned gHD[NWORDS];         // horizontally dilated bits
__device__ unsigned gDL[NWORDS];         // fully dilated bits (== aug_pos)
__device__ int gCntPos[NCHUNK], gCntFp[NCHUNK], gCntNeg[NCHUNK];
__device__ int gOffPos[NCHUNK], gOffFp[NCHUNK], gOffNeg[NCHUNK];
__device__ int gRowPos[NIMG],   gRowFp[NIMG],   gRowNeg[NIMG];
__device__ double gAcc;

__device__ __forceinline__ int reflect512(int c) {
    c = (c < 0) ? -c : c;
    return (c > 511) ? (1022 - c) : c;
}

__device__ __forceinline__ float softplusf(float z) {
    // softplus(z) = max(z,0) + log(1 + exp(-|z|)); fast intrinsics are plenty
    // accurate for rel_err 1e-3 on a mean of ~1e7 O(1) terms.
    return fmaxf(z, 0.f) + __logf(1.f + __expf(-fabsf(z)));
}

// ---- K0: zero the accumulator (d_out is poisoned; gAcc must reset per call) ----
__global__ void k_zero() { gAcc = 0.0; }

// ---- K1: pack t>0 into bits + horizontal 7-wide OR (reflect) ----
__global__ void k_pack(const float* __restrict__ t) {
    int w = blockIdx.x * blockDim.x + threadIdx.x;
    if (w >= NWORDS) return;
    int img = w >> 13;              // / 8192
    int rem = w & 8191;
    int h   = rem >> 4;
    int ww  = rem & 15;
    const float* trow = t + (size_t)img * LIMG + (size_t)h * WDIM;
    int c0 = ww << 5;
    unsigned long long ext = 0ull;  // bit k <-> column c0-3+k (reflected)
    #pragma unroll
    for (int k = 0; k < 38; k++) {
        int col = reflect512(c0 - 3 + k);
        if (trow[col] > 0.f) ext |= (1ull << k);
    }
    gTB[w] = (unsigned)(ext >> 3);
    // OR over shifts 0..6 -> 7-wide horizontal dilation
    unsigned long long m = ext;
    m |= m >> 1;   // shifts 0..1
    m |= m >> 2;   // shifts 0..3
    m |= m >> 3;   // shifts 0..6
    gHD[w] = (unsigned)m;
}

// ---- K2: vertical 7-wide OR (reflect) -> full dilation == aug_pos ----
__global__ void k_vdil() {
    int w = blockIdx.x * blockDim.x + threadIdx.x;
    if (w >= NWORDS) return;
    int img = w >> 13;
    int rem = w & 8191;
    int h   = rem >> 4;
    int ww  = rem & 15;
    unsigned d = 0u;
    #pragma unroll
    for (int dh = -3; dh <= 3; dh++) {
        int hh = reflect512(h + dh);
        d |= gHD[(img << 13) + (hh << 4) + ww];
    }
    gDL[w] = d;
}

// ---- K3: per-chunk counts of pos / false-pos / neg ----
__global__ void k_count(const float* __restrict__ x) {
    int c   = blockIdx.x;
    int tid = threadIdx.x;
    int ebase = c * CHUNK + tid * 16;
    int word  = (c << 7) + (tid >> 1);
    int sh    = (tid & 1) << 4;
    unsigned tb = (gTB[word] >> sh) & 0xFFFFu;
    unsigned db = (gDL[word] >> sh) & 0xFFFFu;
    const float4* xv = (const float4*)(x + ebase);
    unsigned sb = 0u;
    #pragma unroll
    for (int q = 0; q < 4; q++) {
        float4 v = xv[q];
        if (v.x > 0.f) sb |= 1u << (q * 4 + 0);
        if (v.y > 0.f) sb |= 1u << (q * 4 + 1);
        if (v.z > 0.f) sb |= 1u << (q * 4 + 2);
        if (v.w > 0.f) sb |= 1u << (q * 4 + 3);
    }
    int posc = __popc(tb);
    int fpc  = __popc(sb & ~db & 0xFFFFu);
    int negc = __popc(~db & 0xFFFFu);

    int lane = tid & 31, wid = tid >> 5;
    unsigned full = 0xFFFFFFFFu;
    int rp = __reduce_add_sync(full, posc);
    int rf = __reduce_add_sync(full, fpc);
    int rn = __reduce_add_sync(full, negc);
    __shared__ int sp[8], sf[8], sn[8];
    if (lane == 0) { sp[wid] = rp; sf[wid] = rf; sn[wid] = rn; }
    __syncthreads();
    if (tid == 0) {
        int a = 0, b = 0, d2 = 0;
        #pragma unroll
        for (int k = 0; k < 8; k++) { a += sp[k]; b += sf[k]; d2 += sn[k]; }
        gCntPos[c] = a; gCntFp[c] = b; gCntNeg[c] = d2;
    }
}

// ---- K4: per-image exclusive scan of chunk counts (64 chunks/image) ----
__global__ void k_scan() {
    __shared__ int sp[64], sf[64], sn[64];
    int row = blockIdx.x, tid = threadIdx.x;
    int ci = row * CPI + tid;
    int p = gCntPos[ci], f = gCntFp[ci], n = gCntNeg[ci];
    sp[tid] = p; sf[tid] = f; sn[tid] = n;
    __syncthreads();
    for (int o = 1; o < 64; o <<= 1) {
        int ap = (tid >= o) ? sp[tid - o] : 0;
        int af = (tid >= o) ? sf[tid - o] : 0;
        int an = (tid >= o) ? sn[tid - o] : 0;
        __syncthreads();
        sp[tid] += ap; sf[tid] += af; sn[tid] += an;
        __syncthreads();
    }
    int base = row * LIMG;
    gOffPos[ci] = base + sp[tid] - p;
    gOffFp[ci]  = base + sf[tid] - f;
    gOffNeg[ci] = base + sn[tid] - n;
    if (tid == 63) { gRowPos[row] = sp[63]; gRowFp[row] = sf[63]; gRowNeg[row] = sn[63]; }
}

// ---- K5: ordered scatter into gP (positives) and gF (chosen mask) ----
__global__ void k_write(const float* __restrict__ x) {
    int c   = blockIdx.x;
    int tid = threadIdx.x;
    int img = c / CPI;
    bool useFp = gRowFp[img] > 0;
    int ebase = c * CHUNK + tid * 16;
    int word  = (c << 7) + (tid >> 1);
    int sh    = (tid & 1) << 4;
    unsigned tb = (gTB[word] >> sh) & 0xFFFFu;
    unsigned db = (gDL[word] >> sh) & 0xFFFFu;

    float xv[16];
    const float4* xp = (const float4*)(x + ebase);
    #pragma unroll
    for (int q = 0; q < 4; q++) {
        float4 v = xp[q];
        xv[q * 4 + 0] = v.x; xv[q * 4 + 1] = v.y;
        xv[q * 4 + 2] = v.z; xv[q * 4 + 3] = v.w;
    }
    unsigned sb = 0u;
    #pragma unroll
    for (int i = 0; i < 16; i++) if (xv[i] > 0.f) sb |= 1u << i;
    unsigned cm = (useFp ? (sb & ~db) : ~db) & 0xFFFFu;

    int pc = __popc(tb), cc = __popc(cm);
    int packed = pc | (cc << 16);          // block totals <= 4096 each -> fits
    int lane = tid & 31, wid = tid >> 5;
    int v = packed;
    #pragma unroll
    for (int o = 1; o < 32; o <<= 1) {
        int nn = __shfl_up_sync(0xFFFFFFFFu, v, o);
        if (lane >= o) v += nn;
    }
    __shared__ int wtot[8];
    if (lane == 31) wtot[wid] = v;
    __syncthreads();
    int wbase = 0;
    for (int k = 0; k < wid; k++) wbase += wtot[k];
    int excl = wbase + v - packed;

    int pOff = gOffPos[c] + (excl & 0xFFFF);
    int cOff = (useFp ? gOffFp[c] : gOffNeg[c]) + (excl >> 16);
    #pragma unroll
    for (int i = 0; i < 16; i++) {
        if ((tb >> i) & 1) gP[pOff++] = xv[i];
        if ((cm >> i) & 1) gF[cOff++] = xv[i];
    }
}

// ---- K6: fused loss (all three BCE terms), double accumulation ----
__global__ void k_loss(const float* __restrict__ x) {
    int b   = blockIdx.x;
    int img = b >> 7;                         // 128 blocks per image
    int ibase = (b & 127) * LOSS_BLK_ELEMS + threadIdx.x * 8;
    unsigned cp = (unsigned)gRowPos[img];
    unsigned rf = (unsigned)gRowFp[img];
    unsigned cf = rf > 0 ? rf : (unsigned)gRowNeg[img];
    const float* Pb = gP + (size_t)img * LIMG;
    const float* Fb = gF + (size_t)img * LIMG;

    size_t ge = (size_t)img * LIMG + ibase;
    const float4* xp = (const float4*)(x + ge);
    float4 v0 = xp[0], v1 = xp[1];
    float xv[8] = {v0.x, v0.y, v0.z, v0.w, v1.x, v1.y, v1.z, v1.w};
    unsigned tb8 = (gTB[ge >> 5] >> (ibase & 31)) & 0xFFu;   // ibase%32 in {0,8,16,24}

    float acc = 0.f;
    #pragma unroll
    for (int j = 0; j < 8; j++) {
        unsigned e = (unsigned)(ibase + j);
        float p  = cp ? Pb[e % cp] : 5.0f;
        float f  = cf ? Fb[e % cf] : -5.0f;
        float xx = xv[j];
        float s  = p * xx;
        float t1 = softplusf(s) - (((tb8 >> j) & 1u) ? s : 0.f);
        float t2 = softplusf(-p);                  // softplus(p) - p
        float t3 = softplusf(p * f);
        acc += t1 + t2 + 0.1f * t3;
    }

    // block reduce -> one double atomic per block
    int lane = threadIdx.x & 31, wid = threadIdx.x >> 5;
    #pragma unroll
    for (int o = 16; o > 0; o >>= 1) acc += __shfl_down_sync(0xFFFFFFFFu, acc, o);
    __shared__ float ws[8];
    if (lane == 0) ws[wid] = acc;
    __syncthreads();
    if (threadIdx.x == 0) {
        float s = 0.f;
        #pragma unroll
        for (int k = 0; k < 8; k++) s += ws[k];
        atomicAdd(&gAcc, (double)s);
    }
}

// ---- K7: finalize ----
__global__ void k_final(float* __restrict__ out) {
    out[0] = (float)(gAcc / (double)NELEM);
}

extern "C" void kernel_launch(void* const* d_in, const int* in_sizes, int n_in,
                              void* d_out, int out_size) {
    const float* x = (const float*)d_in[0];   // input
    const float* t = (const float*)d_in[1];   // target
    float* out = (float*)d_out;
    (void)in_sizes; (void)n_in; (void)out_size;

    k_zero <<<1, 1>>>();
    k_pack <<<NWORDS / 256, 256>>>(t);
    k_vdil <<<NWORDS / 256, 256>>>();
    k_count<<<NCHUNK, 256>>>(x);
    k_scan <<<NIMG, 64>>>();
    k_write<<<NCHUNK, 256>>>(x);
    k_loss <<<LOSS_BLOCKS, 256>>>(x);
    k_final<<<1, 1>>>(out);
}

// round 2
// speedup vs baseline: 1.5829x; 1.5829x over previous
#include <cuda_runtime.h>
#include <math.h>

// Problem geometry (fixed by setup_inputs): B=16, C=3, H=W=512
#define NIMG   48
#define HDIM   512
#define WDIM   512
#define LIMG   (HDIM*WDIM)        // 262144 per image
#define NELEM  (NIMG*LIMG)        // 12,582,912
#define WPI    8192               // 32-bit mask words per image
#define NWORDS (NIMG*WPI)         // 393,216
#define CHUNK  4096
#define CPI    64                 // chunks per image
#define NCHUNK (NIMG*CPI)         // 3072
#define LOSS_BLOCKS  (NELEM/2048) // 6144
#define PLOSS_BLOCKS (NELEM/2048) // 6144

// ---- static scratch ----
__device__ float    gP[NELEM];    // compacted x at (t>0), per image, original order
__device__ float    gF[NELEM];    // compacted x at chosen mask, per image
__device__ unsigned gTB[NWORDS];  // packed bits: t > 0
__device__ unsigned gDL[NWORDS];  // 7x7-dilated bits (== aug_pos)
__device__ int gCntPos[NCHUNK], gCntFp[NCHUNK], gCntNeg[NCHUNK];
__device__ int gOffPos[NCHUNK], gOffFp[NCHUNK], gOffNeg[NCHUNK];
__device__ int gRowPos[NIMG],   gRowFp[NIMG],   gRowNeg[NIMG];
__device__ double gAcc;

__device__ __forceinline__ int reflect512(int c) {
    c = (c < 0) ? -c : c;
    return (c > 511) ? (1022 - c) : c;
}

__device__ __forceinline__ float softplusf(float z) {
    return fmaxf(z, 0.f) + __logf(1.f + __expf(-fabsf(z)));
}

// ---- K1: warp-cooperative bit pack of (t > 0); also zeroes gAcc ----
__global__ void k_pack(const float* __restrict__ t) {
    if (blockIdx.x == 0 && threadIdx.x == 0) gAcc = 0.0;
    int warp = (blockIdx.x * blockDim.x + threadIdx.x) >> 5;
    int lane = threadIdx.x & 31;
    size_t base = (size_t)warp * 256;
    float v[8];
    #pragma unroll
    for (int q = 0; q < 8; q++) v[q] = t[base + q * 32 + lane];
    unsigned myword = 0;
    #pragma unroll
    for (int q = 0; q < 8; q++) {
        unsigned bal = __ballot_sync(0xFFFFFFFFu, v[q] > 0.f);
        if (lane == q) myword = bal;
    }
    if (lane < 8) gTB[warp * 8 + lane] = myword;
}

// ---- K2: fused 7-wide horizontal + vertical OR-dilation (reflect) ----
__device__ __forceinline__ unsigned hdil(const unsigned* __restrict__ rowTB, int ww) {
    unsigned cur = rowTB[ww];
    unsigned long long ext = ((unsigned long long)cur) << 3;  // bit k <-> col c0-3+k
    if (ww > 0) {
        ext |= (rowTB[ww - 1] >> 29);
    } else {  // reflect: cols -1,-2,-3 -> 1,2,3
        ext |= ((cur >> 3) & 1u) | (((cur >> 2) & 1u) << 1) | (((cur >> 1) & 1u) << 2);
    }
    if (ww < 15) {
        ext |= ((unsigned long long)(rowTB[ww + 1] & 7u)) << 35;
    } else {  // reflect: cols 512,513,514 -> 510,509,508
        ext |= ((unsigned long long)((cur >> 30) & 1u)) << 35
             | ((unsigned long long)((cur >> 29) & 1u)) << 36
             | ((unsigned long long)((cur >> 28) & 1u)) << 37;
    }
    unsigned long long m = ext;
    m |= m >> 1; m |= m >> 2; m |= m >> 3;   // OR over 7-window
    return (unsigned)m;
}

__global__ void k_dil() {
    int w = blockIdx.x * blockDim.x + threadIdx.x;
    int img = w >> 13, rem = w & 8191, h = rem >> 4, ww = rem & 15;
    const unsigned* ib = gTB + (img << 13);
    unsigned d = 0u;
    #pragma unroll
    for (int dh = -3; dh <= 3; dh++) {
        int hh = reflect512(h + dh);
        d |= hdil(ib + (hh << 4), ww);
    }
    gDL[w] = d;
}

// ---- K3: per-chunk counts of pos / false-pos / neg ----
__global__ void k_count(const float* __restrict__ x) {
    int c   = blockIdx.x;
    int tid = threadIdx.x;
    int ebase = c * CHUNK + tid * 16;
    int word  = (c << 7) + (tid >> 1);
    int sh    = (tid & 1) << 4;
    unsigned tb = (gTB[word] >> sh) & 0xFFFFu;
    unsigned db = (gDL[word] >> sh) & 0xFFFFu;
    const float4* xv = (const float4*)(x + ebase);
    unsigned sb = 0u;
    #pragma unroll
    for (int q = 0; q < 4; q++) {
        float4 v = xv[q];
        if (v.x > 0.f) sb |= 1u << (q * 4 + 0);
        if (v.y > 0.f) sb |= 1u << (q * 4 + 1);
        if (v.z > 0.f) sb |= 1u << (q * 4 + 2);
        if (v.w > 0.f) sb |= 1u << (q * 4 + 3);
    }
    int posc = __popc(tb);
    int fpc  = __popc(sb & ~db & 0xFFFFu);
    int negc = __popc(~db & 0xFFFFu);

    int lane = tid & 31, wid = tid >> 5;
    int rp = __reduce_add_sync(0xFFFFFFFFu, posc);
    int rf = __reduce_add_sync(0xFFFFFFFFu, fpc);
    int rn = __reduce_add_sync(0xFFFFFFFFu, negc);
    __shared__ int sp[8], sf[8], sn[8];
    if (lane == 0) { sp[wid] = rp; sf[wid] = rf; sn[wid] = rn; }
    __syncthreads();
    if (tid == 0) {
        int a = 0, b = 0, d2 = 0;
        #pragma unroll
        for (int k = 0; k < 8; k++) { a += sp[k]; b += sf[k]; d2 += sn[k]; }
        gCntPos[c] = a; gCntFp[c] = b; gCntNeg[c] = d2;
    }
}

// ---- K4: per-image exclusive scan of chunk counts ----
__global__ void k_scan() {
    __shared__ int sp[64], sf[64], sn[64];
    int row = blockIdx.x, tid = threadIdx.x;
    int ci = row * CPI + tid;
    int p = gCntPos[ci], f = gCntFp[ci], n = gCntNeg[ci];
    sp[tid] = p; sf[tid] = f; sn[tid] = n;
    __syncthreads();
    for (int o = 1; o < 64; o <<= 1) {
        int ap = (tid >= o) ? sp[tid - o] : 0;
        int af = (tid >= o) ? sf[tid - o] : 0;
        int an = (tid >= o) ? sn[tid - o] : 0;
        __syncthreads();
        sp[tid] += ap; sf[tid] += af; sn[tid] += an;
        __syncthreads();
    }
    int base = row * LIMG;
    gOffPos[ci] = base + sp[tid] - p;
    gOffFp[ci]  = base + sf[tid] - f;
    gOffNeg[ci] = base + sn[tid] - n;
    if (tid == 63) { gRowPos[row] = sp[63]; gRowFp[row] = sf[63]; gRowNeg[row] = sn[63]; }
}

// ---- K5: ordered compaction with shared-memory staging (coalesced output) ----
__global__ void k_write(const float* __restrict__ x) {
    __shared__ float sP[CHUNK];
    __shared__ float sF[CHUNK];
    __shared__ int wtot[8];
    int c   = blockIdx.x;
    int tid = threadIdx.x;
    int img = c / CPI;
    bool useFp = gRowFp[img] > 0;
    int ebase = c * CHUNK + tid * 16;
    int word  = (c << 7) + (tid >> 1);
    int sh    = (tid & 1) << 4;
    unsigned tb = (gTB[word] >> sh) & 0xFFFFu;
    unsigned db = (gDL[word] >> sh) & 0xFFFFu;

    float xv[16];
    const float4* xp = (const float4*)(x + ebase);
    #pragma unroll
    for (int q = 0; q < 4; q++) {
        float4 v = xp[q];
        xv[q * 4 + 0] = v.x; xv[q * 4 + 1] = v.y;
        xv[q * 4 + 2] = v.z; xv[q * 4 + 3] = v.w;
    }
    unsigned sb = 0u;
    #pragma unroll
    for (int i = 0; i < 16; i++) if (xv[i] > 0.f) sb |= 1u << i;
    unsigned cm = (useFp ? (sb & ~db) : ~db) & 0xFFFFu;

    int packed = __popc(tb) | (__popc(cm) << 16);
    int lane = tid & 31, wid = tid >> 5;
    int v = packed;
    #pragma unroll
    for (int o = 1; o < 32; o <<= 1) {
        int nn = __shfl_up_sync(0xFFFFFFFFu, v, o);
        if (lane >= o) v += nn;
    }
    if (lane == 31) wtot[wid] = v;
    __syncthreads();
    int wbase = 0;
    for (int k = 0; k < wid; k++) wbase += wtot[k];
    int excl = wbase + v - packed;

    int pLoc = excl & 0xFFFF;
    int cLoc = excl >> 16;
    #pragma unroll
    for (int i = 0; i < 16; i++) {
        if ((tb >> i) & 1) sP[pLoc++] = xv[i];
        if ((cm >> i) & 1) sF[cLoc++] = xv[i];
    }
    __syncthreads();

    int totP = gCntPos[c];
    int totC = useFp ? gCntFp[c] : gCntNeg[c];
    float* __restrict__ dP = gP + gOffPos[c];
    float* __restrict__ dF = gF + (useFp ? gOffFp[c] : gOffNeg[c]);
    for (int i = tid; i < totP; i += 256) dP[i] = sP[i];
    for (int i = tid; i < totC; i += 256) dF[i] = sF[i];
}

// ---- K6: fused loss. Blocks [0,LOSS_BLOCKS): per-element terms paired with x.
//      Blocks [LOSS_BLOCKS, +PLOSS_BLOCKS): P-only terms folded via cyclic
//      multiplicity m_i = floor(L/cp) + (i < L mod cp). ----
__global__ void k_loss(const float* __restrict__ x) {
    int b = blockIdx.x;
    float acc = 0.f;
    if (b < LOSS_BLOCKS) {
        int img = b >> 7;
        int e0  = (b & 127) * 2048 + threadIdx.x;      // within-image index
        unsigned cp = (unsigned)gRowPos[img];
        unsigned rf = (unsigned)gRowFp[img];
        unsigned rn = (unsigned)gRowNeg[img];
        unsigned cf = rf ? rf : rn;
        const float* __restrict__ Pb = gP + (size_t)img * LIMG;
        const float* __restrict__ Fb = gF + (size_t)img * LIMG;
        const float* __restrict__ xb = x + (size_t)img * LIMG;
        const unsigned* __restrict__ tbw = gTB + ((size_t)img * LIMG >> 5);
        unsigned rP = cp ? ((unsigned)e0 % cp) : 0u;
        unsigned rF = cf ? ((unsigned)e0 % cf) : 0u;
        #pragma unroll
        for (int j = 0; j < 8; j++) {
            int e = e0 + 256 * j;
            float xx = xb[e];
            unsigned tbit = (tbw[e >> 5] >> (e & 31)) & 1u;
            float p = cp ? Pb[rP] : 5.0f;
            float s = p * xx;
            acc += softplusf(s) - (tbit ? s : 0.f);
            if (cf) {
                float f = Fb[rF];
                acc += 0.1f * softplusf(p * f);
                rF += 256u; while (rF >= cf) rF -= cf;
            }
            if (cp) { rP += 256u; while (rP >= cp) rP -= cp; }
        }
    } else {
        int pb  = b - LOSS_BLOCKS;
        int img = pb >> 7;
        int i0  = (pb & 127) * 2048 + threadIdx.x;
        unsigned cp = (unsigned)gRowPos[img];
        unsigned rf = (unsigned)gRowFp[img];
        unsigned rn = (unsigned)gRowNeg[img];
        bool cf0 = (rf == 0u && rn == 0u);             // F is the -5 fallback
        if (cp) {
            unsigned q = (unsigned)LIMG / cp, rr = (unsigned)LIMG - q * cp;
            const float* __restrict__ Pb = gP + (size_t)img * LIMG;
            #pragma unroll
            for (int j = 0; j < 8; j++) {
                unsigned i = (unsigned)i0 + 256u * j;
                if (i < cp) {
                    float pv = Pb[i];
                    float m = (float)(q + (i < rr ? 1u : 0u));
                    float term = softplusf(-pv);                 // bce(dup_pos, 1)
                    if (cf0) term += 0.1f * softplusf(-5.0f * pv);
                    acc += m * term;
                }
            }
        } else if ((pb & 127) == 0 && threadIdx.x == 0) {
            // no positives: p == 5 everywhere
            float t2 = softplusf(-5.f);
            float t3 = cf0 ? 0.1f * softplusf(-25.f) : 0.f;
            acc = (float)LIMG * (t2 + t3);
        }
    }

    int lane = threadIdx.x & 31, wid = threadIdx.x >> 5;
    #pragma unroll
    for (int o = 16; o > 0; o >>= 1) acc += __shfl_down_sync(0xFFFFFFFFu, acc, o);
    __shared__ float ws[8];
    if (lane == 0) ws[wid] = acc;
    __syncthreads();
    if (threadIdx.x == 0) {
        float s = 0.f;
        #pragma unroll
        for (int k = 0; k < 8; k++) s += ws[k];
        atomicAdd(&gAcc, (double)s);
    }
}

// ---- K7: finalize ----
__global__ void k_final(float* __restrict__ out) {
    out[0] = (float)(gAcc / (double)NELEM);
}

extern "C" void kernel_launch(void* const* d_in, const int* in_sizes, int n_in,
                              void* d_out, int out_size) {
    const float* x = (const float*)d_in[0];   // input
    const float* t = (const float*)d_in[1];   // target
    float* out = (float*)d_out;
    (void)in_sizes; (void)n_in; (void)out_size;

    k_pack <<<NELEM / 2048, 256>>>(t);
    k_dil  <<<NWORDS / 256, 256>>>();
    k_count<<<NCHUNK, 256>>>(x);
    k_scan <<<NIMG, 64>>>();
    k_write<<<NCHUNK, 256>>>(x);
    k_loss <<<LOSS_BLOCKS + PLOSS_BLOCKS, 256>>>(x);
    k_final<<<1, 1>>>(out);
}